// round 2
// baseline (speedup 1.0000x reference)
#include <cuda_runtime.h>
#include <cuda_bf16.h>
#include <math.h>

// Problem constants (fixed by the reference)
#define T_TOK   2048
#define KTOP    2
#define NEXP    8
#define HDIM    1024
#define FDIM    4096
#define NASSIGN (T_TOK * KTOP)   // 4096 (token, k) assignments

// GEMM tiling
#define BM 128
#define BN 128
#define BK 16
#define NTHREADS 256

// ---------------------------------------------------------------------------
// Scratch (static device globals — no allocation in kernel_launch)
// ---------------------------------------------------------------------------
__device__ __align__(128) int   g_counts[NEXP];
__device__ __align__(128) int   g_offsets[NEXP + 1];
__device__ __align__(128) int   g_cursor[NEXP];
__device__ __align__(128) int   g_row_token[NASSIGN];   // slot -> token id
__device__ __align__(128) int   g_token_slot[NASSIGN];  // (t*K+k) -> slot
__device__ __align__(128) float g_H[(size_t)NASSIGN * FDIM]; // 64 MB, gelu(x@w1) rows per slot
__device__ __align__(128) float g_Y[(size_t)NASSIGN * HDIM]; // 16 MB, (h@w2) rows per slot

// ---------------------------------------------------------------------------
// Routing with dtype sniffing.
//
// The reference asks for int64 top_experts but JAX-without-x64 silently emits
// int32. We cannot trust the declared dtype, so detect it: read the first
// 2048 int64 *words* (16 KB, in-bounds whether the 4096-element buffer is
// int32 (16KB) or int64 (32KB)). True int64 data => every word in [0,NEXP).
// int32 data => words combine two indices (lo + hi<<32), mostly >= NEXP.
// Deterministic for a given input buffer.
//
// Then: histogram -> prefix -> scatter. Slot order within an expert comes
// from atomics (order nondeterministic) but each slot's math depends only on
// its own (token,k), so the final output is deterministic.
// ---------------------------------------------------------------------------
__global__ void route_kernel(const void* __restrict__ top_experts_raw) {
    const long long* te64 = (const long long*)top_experts_raw;
    const int*       te32 = (const int*)top_experts_raw;
    const int tid = threadIdx.x;

    __shared__ int s_not64;
    if (tid == 0) s_not64 = 0;
    if (tid < NEXP) { g_counts[tid] = 0; g_cursor[tid] = 0; }
    __syncthreads();

    // dtype sniff: first 2048 int64 words are in-bounds for either dtype
    int bad = 0;
    for (int i = tid; i < NASSIGN / 2; i += NTHREADS) {
        long long v = te64[i];
        if (v < 0 || v >= NEXP) bad = 1;
    }
    if (bad) atomicOr(&s_not64, 1);
    __syncthreads();
    const bool is64 = (s_not64 == 0);

    // histogram
    for (int i = tid; i < NASSIGN; i += NTHREADS) {
        int e = is64 ? (int)te64[i] : te32[i];
        atomicAdd(&g_counts[e], 1);
    }
    __syncthreads();
    if (tid == 0) {
        int acc = 0;
        for (int e = 0; e < NEXP; e++) { g_offsets[e] = acc; acc += g_counts[e]; }
        g_offsets[NEXP] = acc;
    }
    __syncthreads();
    // scatter
    for (int i = tid; i < NASSIGN; i += NTHREADS) {
        int e = is64 ? (int)te64[i] : te32[i];
        int pos = g_offsets[e] + atomicAdd(&g_cursor[e], 1);
        g_row_token[pos] = i >> 1;   // token = i / KTOP (KTOP==2)
        g_token_slot[i] = pos;
    }
}

__device__ __forceinline__ float gelu_exact(float v) {
    // exact gelu: 0.5*v*(1+erf(v/sqrt(2)))  == jax.nn.gelu(approximate=False)
    return 0.5f * v * (1.0f + erff(v * 0.70710678118654752f));
}

// ---------------------------------------------------------------------------
// Grouped GEMM. Per expert e (blockIdx.z):
//   GATHER=true  : A rows gathered from x via g_row_token   (GEMM1, C=g_H, +gelu)
//   GATHER=false : A rows are contiguous slots of g_H       (GEMM2, C=g_Y)
// W is [NEXP, KDIM, NDIM] row-major. 128x128x16 tiles, 8x8 per thread,
// double-buffered shared memory, float4 everywhere.
// ---------------------------------------------------------------------------
template <int KDIM, int NDIM, bool GELU, bool GATHER>
__global__ __launch_bounds__(NTHREADS)
void expert_gemm(const float* __restrict__ A_src, const float* __restrict__ W) {
    const int e    = blockIdx.z;
    const int base = g_offsets[e];
    const int Me   = g_offsets[e + 1] - base;
    const int m0   = blockIdx.y * BM;
    if (m0 >= Me) return;
    const int n0   = blockIdx.x * BN;

    const float* __restrict__ A = GATHER ? A_src : g_H;
    float* __restrict__ C       = GELU ? g_H : g_Y;

    __shared__ float As[2][BK][BM];
    __shared__ float Bs[2][BK][BN];
    __shared__ int   rowSrc[BM];

    const int tid = threadIdx.x;

    // Resolve source row for each tile row (clamp OOB rows to a valid row;
    // epilogue masks them out).
    for (int r = tid; r < BM; r += NTHREADS) {
        int m = m0 + r;
        int safe_m = (m < Me) ? m : 0;
        rowSrc[r] = GATHER ? g_row_token[base + safe_m] : (base + safe_m);
    }
    __syncthreads();

    const float* __restrict__ Wt = W + (size_t)e * KDIM * NDIM;

    const int KT = KDIM / BK;
    float4 ar[2], br[2];

    // per-thread static load coordinates
    // A: 512 float4 per tile (128 rows x 4 quads), 2 per thread
    const int a_row0 = (tid + 0)   >> 2;
    const int a_kq0  = ((tid + 0)  & 3) << 2;
    const int a_row1 = (tid + 256) >> 2;
    const int a_kq1  = ((tid + 256) & 3) << 2;
    // B: 512 float4 per tile (16 rows x 32 quads), 2 per thread
    const int b_kr0  = (tid + 0)   >> 5;
    const int b_nq0  = ((tid + 0)  & 31) << 2;
    const int b_kr1  = (tid + 256) >> 5;
    const int b_nq1  = ((tid + 256) & 31) << 2;

    #define FETCH_A(kt)                                                          \
        do {                                                                     \
            ar[0] = *(const float4*)(A + (size_t)rowSrc[a_row0] * KDIM + (kt) * BK + a_kq0); \
            ar[1] = *(const float4*)(A + (size_t)rowSrc[a_row1] * KDIM + (kt) * BK + a_kq1); \
        } while (0)
    #define FETCH_B(kt)                                                          \
        do {                                                                     \
            br[0] = *(const float4*)(Wt + (size_t)((kt) * BK + b_kr0) * NDIM + n0 + b_nq0); \
            br[1] = *(const float4*)(Wt + (size_t)((kt) * BK + b_kr1) * NDIM + n0 + b_nq1); \
        } while (0)
    #define STORE_AB(buf)                                                        \
        do {                                                                     \
            As[buf][a_kq0 + 0][a_row0] = ar[0].x;                                \
            As[buf][a_kq0 + 1][a_row0] = ar[0].y;                                \
            As[buf][a_kq0 + 2][a_row0] = ar[0].z;                                \
            As[buf][a_kq0 + 3][a_row0] = ar[0].w;                                \
            As[buf][a_kq1 + 0][a_row1] = ar[1].x;                                \
            As[buf][a_kq1 + 1][a_row1] = ar[1].y;                                \
            As[buf][a_kq1 + 2][a_row1] = ar[1].z;                                \
            As[buf][a_kq1 + 3][a_row1] = ar[1].w;                                \
            *(float4*)&Bs[buf][b_kr0][b_nq0] = br[0];                            \
            *(float4*)&Bs[buf][b_kr1][b_nq1] = br[1];                            \
        } while (0)

    float acc[8][8];
    #pragma unroll
    for (int i = 0; i < 8; i++)
        #pragma unroll
        for (int j = 0; j < 8; j++) acc[i][j] = 0.0f;

    const int ty = tid >> 4;   // 0..15  -> rows ty*8 .. ty*8+7
    const int tx = tid & 15;   // 0..15  -> cols tx*8 .. tx*8+7

    FETCH_A(0); FETCH_B(0);
    STORE_AB(0);
    __syncthreads();

    for (int kt = 0; kt < KT; kt++) {
        const int cur = kt & 1;
        if (kt + 1 < KT) { FETCH_A(kt + 1); FETCH_B(kt + 1); }

        #pragma unroll
        for (int kk = 0; kk < BK; kk++) {
            float a[8], b[8];
            *(float4*)&a[0] = *(const float4*)&As[cur][kk][ty * 8 + 0];
            *(float4*)&a[4] = *(const float4*)&As[cur][kk][ty * 8 + 4];
            *(float4*)&b[0] = *(const float4*)&Bs[cur][kk][tx * 8 + 0];
            *(float4*)&b[4] = *(const float4*)&Bs[cur][kk][tx * 8 + 4];
            #pragma unroll
            for (int i = 0; i < 8; i++)
                #pragma unroll
                for (int j = 0; j < 8; j++)
                    acc[i][j] = fmaf(a[i], b[j], acc[i][j]);
        }

        if (kt + 1 < KT) STORE_AB(cur ^ 1);
        __syncthreads();
    }

    // Epilogue
    #pragma unroll
    for (int i = 0; i < 8; i++) {
        int m = m0 + ty * 8 + i;
        if (m < Me) {
            float* crow = C + (size_t)(base + m) * NDIM + n0 + tx * 8;
            float v[8];
            #pragma unroll
            for (int j = 0; j < 8; j++)
                v[j] = GELU ? gelu_exact(acc[i][j]) : acc[i][j];
            *(float4*)&crow[0] = *(float4*)&v[0];
            *(float4*)&crow[4] = *(float4*)&v[4];
        }
    }
    #undef FETCH_A
    #undef FETCH_B
    #undef STORE_AB
}

// ---------------------------------------------------------------------------
// Combine: out[t] = ew[t,0]*Y[slot(t,0)] + ew[t,1]*Y[slot(t,1)]
// ---------------------------------------------------------------------------
__global__ void combine_kernel(const float* __restrict__ ew, float* __restrict__ out) {
    int idx = blockIdx.x * blockDim.x + threadIdx.x;   // over T*H/4
    if (idx >= T_TOK * (HDIM / 4)) return;
    int t  = idx / (HDIM / 4);
    int c4 = (idx % (HDIM / 4)) * 4;
    float w0 = ew[t * 2 + 0];
    float w1 = ew[t * 2 + 1];
    int   s0 = g_token_slot[t * 2 + 0];
    int   s1 = g_token_slot[t * 2 + 1];
    float4 y0 = *(const float4*)(g_Y + (size_t)s0 * HDIM + c4);
    float4 y1 = *(const float4*)(g_Y + (size_t)s1 * HDIM + c4);
    float4 o;
    o.x = w0 * y0.x + w1 * y1.x;
    o.y = w0 * y0.y + w1 * y1.y;
    o.z = w0 * y0.z + w1 * y1.z;
    o.w = w0 * y0.w + w1 * y1.w;
    *(float4*)(out + (size_t)t * HDIM + c4) = o;
}

// ---------------------------------------------------------------------------
// kernel_launch: route -> GEMM1 (x@w1, gelu) -> GEMM2 (h@w2) -> combine
// Inputs (metadata order): x[2,1024,1024] f32, scores[2048,8] f32 (unused),
// expert_weights[2048,2] f32, top_experts[2048,2] int (dtype sniffed),
// w1[8,1024,4096] f32, w2[8,4096,1024] f32. Output: [2,1024,1024] f32.
// ---------------------------------------------------------------------------
extern "C" void kernel_launch(void* const* d_in, const int* in_sizes, int n_in,
                              void* d_out, int out_size) {
    const float* x   = (const float*)d_in[0];
    const float* ew  = (const float*)d_in[2];
    const void*  te  = d_in[3];
    const float* w1  = (const float*)d_in[4];
    const float* w2  = (const float*)d_in[5];
    float*       out = (float*)d_out;

    route_kernel<<<1, NTHREADS>>>(te);

    // GEMM1: [Me, H] x [H, F] -> gelu -> g_H.  grid: n-tiles x m-tiles x experts
    dim3 g1(FDIM / BN, NASSIGN / BM, NEXP);   // 32 x 32 x 8
    expert_gemm<HDIM, FDIM, true, true><<<g1, NTHREADS>>>(x, w1);

    // GEMM2: [Me, F] x [F, H] -> g_Y
    dim3 g2(HDIM / BN, NASSIGN / BM, NEXP);   // 8 x 32 x 8
    expert_gemm<FDIM, HDIM, false, false><<<g2, NTHREADS>>>(nullptr, w2);

    // Combine into output
    int total = T_TOK * (HDIM / 4);
    combine_kernel<<<(total + NTHREADS - 1) / NTHREADS, NTHREADS>>>(ew, out);
}

// round 3
// speedup vs baseline: 2.7448x; 2.7448x over previous
#include <cuda_runtime.h>
#include <cuda_bf16.h>
#include <math.h>
#include <stdint.h>

// Problem constants (fixed by the reference)
#define T_TOK   2048
#define KTOP    2
#define NEXP    8
#define HDIM    1024
#define FDIM    4096
#define NASSIGN (T_TOK * KTOP)   // 4096 (token, k) assignments

// GEMM tiling
#define BM 128
#define BN 128
#define BK 16
#define NTHREADS 256
#define APAD 20    // As row stride (k padded 16->20): conflict-free frag loads
#define BPAD 136   // Bs row stride (n padded 128->136): conflict-free frag loads

// ---------------------------------------------------------------------------
// Scratch (static device globals — no allocation anywhere)
// ---------------------------------------------------------------------------
__device__ __align__(128) int   g_counts[NEXP];
__device__ __align__(128) int   g_offsets[NEXP + 1];
__device__ __align__(128) int   g_cursor[NEXP];
__device__ __align__(128) int   g_row_token[NASSIGN];   // slot -> token id
__device__ __align__(128) int   g_token_slot[NASSIGN];  // (t*K+k) -> slot
__device__ __align__(128) float g_H[(size_t)NASSIGN * FDIM]; // gelu(x@w1) rows per slot
__device__ __align__(128) float g_Y[(size_t)NASSIGN * HDIM]; // (h@w2) rows per slot

// ---------------------------------------------------------------------------
// Routing with dtype sniffing (reference declares int64 top_experts but JAX
// w/o x64 silently emits int32; detect which one is actually in the buffer).
// ---------------------------------------------------------------------------
__global__ void route_kernel(const void* __restrict__ top_experts_raw) {
    const long long* te64 = (const long long*)top_experts_raw;
    const int*       te32 = (const int*)top_experts_raw;
    const int tid = threadIdx.x;

    __shared__ int s_not64;
    if (tid == 0) s_not64 = 0;
    if (tid < NEXP) { g_counts[tid] = 0; g_cursor[tid] = 0; }
    __syncthreads();

    int bad = 0;
    for (int i = tid; i < NASSIGN / 2; i += NTHREADS) {
        long long v = te64[i];
        if (v < 0 || v >= NEXP) bad = 1;
    }
    if (bad) atomicOr(&s_not64, 1);
    __syncthreads();
    const bool is64 = (s_not64 == 0);

    for (int i = tid; i < NASSIGN; i += NTHREADS) {
        int e = is64 ? (int)te64[i] : te32[i];
        atomicAdd(&g_counts[e], 1);
    }
    __syncthreads();
    if (tid == 0) {
        int acc = 0;
        for (int e = 0; e < NEXP; e++) { g_offsets[e] = acc; acc += g_counts[e]; }
        g_offsets[NEXP] = acc;
    }
    __syncthreads();
    for (int i = tid; i < NASSIGN; i += NTHREADS) {
        int e = is64 ? (int)te64[i] : te32[i];
        int pos = g_offsets[e] + atomicAdd(&g_cursor[e], 1);
        g_row_token[pos] = i >> 1;
        g_token_slot[i] = pos;
    }
}

__device__ __forceinline__ float gelu_exact(float v) {
    return 0.5f * v * (1.0f + erff(v * 0.70710678118654752f));
}

// fp32 -> tf32 with round-to-nearest (keeps the value as f32 bit pattern)
__device__ __forceinline__ float to_tf32(float x) {
    uint32_t u;
    asm("cvt.rna.tf32.f32 %0, %1;" : "=r"(u) : "f"(x));
    return __uint_as_float(u);
}

__device__ __forceinline__ void mma_tf32_16x8x8(
    float* d, const uint32_t* a, const uint32_t* b) {
    asm volatile(
        "mma.sync.aligned.m16n8k8.row.col.f32.tf32.tf32.f32 "
        "{%0,%1,%2,%3}, {%4,%5,%6,%7}, {%8,%9}, {%0,%1,%2,%3};\n"
        : "+f"(d[0]), "+f"(d[1]), "+f"(d[2]), "+f"(d[3])
        : "r"(a[0]), "r"(a[1]), "r"(a[2]), "r"(a[3]),
          "r"(b[0]), "r"(b[1]));
}

// ---------------------------------------------------------------------------
// Grouped GEMM on tensor cores (mma.sync tf32, fp32 accumulate).
// Block 128x128, BK=16. 8 warps: warp grid 2(M) x 4(N), warp tile 64x32.
// Per k8 step each warp holds 4 A frags (m16k8) + 4 B frags (k8n8) -> 16 mmas.
//   GATHER=true  : A rows gathered from x via g_row_token  (GEMM1, C=g_H, +gelu)
//   GATHER=false : A rows are contiguous slots of g_H      (GEMM2, C=g_Y)
// W is [NEXP, KDIM, NDIM] row-major.
// ---------------------------------------------------------------------------
template <int KDIM, int NDIM, bool GELU, bool GATHER>
__global__ __launch_bounds__(NTHREADS)
void expert_gemm_mma(const float* __restrict__ A_src, const float* __restrict__ W) {
    const int e    = blockIdx.z;
    const int base = g_offsets[e];
    const int Me   = g_offsets[e + 1] - base;
    const int m0   = blockIdx.y * BM;
    if (m0 >= Me) return;
    const int n0   = blockIdx.x * BN;

    const float* __restrict__ A = GATHER ? A_src : g_H;
    float* __restrict__ C       = GELU ? g_H : g_Y;

    __shared__ float As[2][BM][APAD];   // [m][k] tf32 values
    __shared__ float Bs[2][BK][BPAD];   // [k][n] tf32 values
    __shared__ int   rowSrc[BM];

    const int tid = threadIdx.x;

    for (int r = tid; r < BM; r += NTHREADS) {
        int m = m0 + r;
        int safe_m = (m < Me) ? m : 0;
        rowSrc[r] = GATHER ? g_row_token[base + safe_m] : (base + safe_m);
    }
    __syncthreads();

    const float* __restrict__ Wt = W + (size_t)e * KDIM * NDIM;
    const int KT = KDIM / BK;

    // global->smem load coordinates (2 float4 each for A and B per thread)
    const int a_row = tid >> 2;            // 0..63 (+64 for second)
    const int a_kq  = (tid & 3) << 2;      // 0,4,8,12
    const int b_kr  = tid >> 5;            // 0..7 (+8 for second)
    const int b_nq  = (tid & 31) << 2;     // 0..124

    float4 ar[2], br[2];

    #define FETCH(kt)                                                                     \
        do {                                                                              \
            ar[0] = *(const float4*)(A + (size_t)rowSrc[a_row]      * KDIM + (kt) * BK + a_kq); \
            ar[1] = *(const float4*)(A + (size_t)rowSrc[a_row + 64] * KDIM + (kt) * BK + a_kq); \
            br[0] = *(const float4*)(Wt + (size_t)((kt) * BK + b_kr)     * NDIM + n0 + b_nq);   \
            br[1] = *(const float4*)(Wt + (size_t)((kt) * BK + b_kr + 8) * NDIM + n0 + b_nq);   \
        } while (0)
    #define STORE_AB(buf)                                                                 \
        do {                                                                              \
            float4 t0, t1;                                                                \
            t0.x = to_tf32(ar[0].x); t0.y = to_tf32(ar[0].y);                             \
            t0.z = to_tf32(ar[0].z); t0.w = to_tf32(ar[0].w);                             \
            t1.x = to_tf32(ar[1].x); t1.y = to_tf32(ar[1].y);                             \
            t1.z = to_tf32(ar[1].z); t1.w = to_tf32(ar[1].w);                             \
            *(float4*)&As[buf][a_row][a_kq]      = t0;                                    \
            *(float4*)&As[buf][a_row + 64][a_kq] = t1;                                    \
            t0.x = to_tf32(br[0].x); t0.y = to_tf32(br[0].y);                             \
            t0.z = to_tf32(br[0].z); t0.w = to_tf32(br[0].w);                             \
            t1.x = to_tf32(br[1].x); t1.y = to_tf32(br[1].y);                             \
            t1.z = to_tf32(br[1].z); t1.w = to_tf32(br[1].w);                             \
            *(float4*)&Bs[buf][b_kr][b_nq]     = t0;                                      \
            *(float4*)&Bs[buf][b_kr + 8][b_nq] = t1;                                      \
        } while (0)

    // warp/fragment coordinates
    const int w    = tid >> 5;
    const int lane = tid & 31;
    const int wm   = (w >> 2) * 64;        // 0 or 64
    const int wn   = (w & 3) * 32;         // 0,32,64,96
    const int fr   = lane >> 2;            // 0..7
    const int fc   = lane & 3;             // 0..3

    float acc[4][4][4];
    #pragma unroll
    for (int i = 0; i < 4; i++)
        #pragma unroll
        for (int j = 0; j < 4; j++)
            #pragma unroll
            for (int q = 0; q < 4; q++) acc[i][j][q] = 0.0f;

    FETCH(0);
    STORE_AB(0);
    __syncthreads();

    for (int kt = 0; kt < KT; kt++) {
        const int cur = kt & 1;
        if (kt + 1 < KT) FETCH(kt + 1);

        #pragma unroll
        for (int s = 0; s < 2; s++) {      // two k8 steps per BK=16
            const int k0 = s * 8;
            uint32_t afr[4][4], bfr[4][2];
            #pragma unroll
            for (int i = 0; i < 4; i++) {
                const int mA = wm + i * 16 + fr;
                afr[i][0] = __float_as_uint(As[cur][mA][k0 + fc]);
                afr[i][1] = __float_as_uint(As[cur][mA + 8][k0 + fc]);
                afr[i][2] = __float_as_uint(As[cur][mA][k0 + fc + 4]);
                afr[i][3] = __float_as_uint(As[cur][mA + 8][k0 + fc + 4]);
            }
            #pragma unroll
            for (int j = 0; j < 4; j++) {
                const int nB = wn + j * 8 + fr;
                bfr[j][0] = __float_as_uint(Bs[cur][k0 + fc][nB]);
                bfr[j][1] = __float_as_uint(Bs[cur][k0 + fc + 4][nB]);
            }
            #pragma unroll
            for (int i = 0; i < 4; i++)
                #pragma unroll
                for (int j = 0; j < 4; j++)
                    mma_tf32_16x8x8(acc[i][j], afr[i], bfr[j]);
        }

        if (kt + 1 < KT) STORE_AB(cur ^ 1);
        __syncthreads();
    }

    // Epilogue: fragment mapping m16n8 -> rows (fr, fr+8), cols (2*fc, 2*fc+1)
    #pragma unroll
    for (int i = 0; i < 4; i++) {
        const int mrow0 = m0 + wm + i * 16 + fr;
        #pragma unroll
        for (int j = 0; j < 4; j++) {
            const int col = n0 + wn + j * 8 + fc * 2;
            float v0 = acc[i][j][0], v1 = acc[i][j][1];
            float v2 = acc[i][j][2], v3 = acc[i][j][3];
            if (GELU) {
                v0 = gelu_exact(v0); v1 = gelu_exact(v1);
                v2 = gelu_exact(v2); v3 = gelu_exact(v3);
            }
            if (mrow0 < Me) {
                float2 p = make_float2(v0, v1);
                *(float2*)(C + (size_t)(base + mrow0) * NDIM + col) = p;
            }
            if (mrow0 + 8 < Me) {
                float2 p = make_float2(v2, v3);
                *(float2*)(C + (size_t)(base + mrow0 + 8) * NDIM + col) = p;
            }
        }
    }
    #undef FETCH
    #undef STORE_AB
}

// ---------------------------------------------------------------------------
// Combine: out[t] = ew[t,0]*Y[slot(t,0)] + ew[t,1]*Y[slot(t,1)]
// ---------------------------------------------------------------------------
__global__ void combine_kernel(const float* __restrict__ ew, float* __restrict__ out) {
    int idx = blockIdx.x * blockDim.x + threadIdx.x;   // over T*H/4
    if (idx >= T_TOK * (HDIM / 4)) return;
    int t  = idx / (HDIM / 4);
    int c4 = (idx % (HDIM / 4)) * 4;
    float w0 = ew[t * 2 + 0];
    float w1 = ew[t * 2 + 1];
    int   s0 = g_token_slot[t * 2 + 0];
    int   s1 = g_token_slot[t * 2 + 1];
    float4 y0 = *(const float4*)(g_Y + (size_t)s0 * HDIM + c4);
    float4 y1 = *(const float4*)(g_Y + (size_t)s1 * HDIM + c4);
    float4 o;
    o.x = w0 * y0.x + w1 * y1.x;
    o.y = w0 * y0.y + w1 * y1.y;
    o.z = w0 * y0.z + w1 * y1.z;
    o.w = w0 * y0.w + w1 * y1.w;
    *(float4*)(out + (size_t)t * HDIM + c4) = o;
}

// ---------------------------------------------------------------------------
// kernel_launch: route -> GEMM1 (x@w1, gelu) -> GEMM2 (h@w2) -> combine
// ---------------------------------------------------------------------------
extern "C" void kernel_launch(void* const* d_in, const int* in_sizes, int n_in,
                              void* d_out, int out_size) {
    const float* x   = (const float*)d_in[0];
    const float* ew  = (const float*)d_in[2];
    const void*  te  = d_in[3];
    const float* w1  = (const float*)d_in[4];
    const float* w2  = (const float*)d_in[5];
    float*       out = (float*)d_out;

    route_kernel<<<1, NTHREADS>>>(te);

    // GEMM1: [Me, H] x [H, F] -> gelu -> g_H
    dim3 g1(FDIM / BN, NASSIGN / BM, NEXP);   // 32 x 32 x 8
    expert_gemm_mma<HDIM, FDIM, true, true><<<g1, NTHREADS>>>(x, w1);

    // GEMM2: [Me, F] x [F, H] -> g_Y
    dim3 g2(HDIM / BN, NASSIGN / BM, NEXP);   // 8 x 32 x 8
    expert_gemm_mma<FDIM, HDIM, false, false><<<g2, NTHREADS>>>(nullptr, w2);

    // Combine into output
    int total = T_TOK * (HDIM / 4);
    combine_kernel<<<(total + NTHREADS - 1) / NTHREADS, NTHREADS>>>(ew, out);
}

// round 6
// speedup vs baseline: 5.0834x; 1.8520x over previous
#include <cuda_runtime.h>
#include <cuda_fp16.h>
#include <math.h>
#include <stdint.h>

// Problem constants
#define T_TOK   2048
#define KTOP    2
#define NEXP    8
#define HDIM    1024
#define FDIM    4096
#define NASSIGN (T_TOK * KTOP)   // 4096

// Tiling
#define BM 128
#define BN 128
#define BK 32                    // fp16 k per chunk = 2 k16 mma steps
#define NTHREADS 256

// Smem row strides (bytes) — conflict-free ldmatrix phases, 16B aligned
#define A_RB 80                  // 32 halfs + 16B pad: (5r)%8 distinct
#define B_RB 272                 // 128 halfs + 16B pad: (17k)%8 distinct

// ---------------------------------------------------------------------------
// Scratch (static device globals — no runtime allocation)
// ---------------------------------------------------------------------------
__device__ __align__(128) int    g_counts[NEXP];
__device__ __align__(128) int    g_offsets[NEXP + 1];
__device__ __align__(128) int    g_cursor[NEXP];
__device__ __align__(128) int    g_row_token[NASSIGN];
__device__ __align__(128) int    g_token_slot[NASSIGN];
__device__ __align__(128) __half g_xh [(size_t)T_TOK * HDIM];        // x in fp16
__device__ __align__(128) __half g_w1h[(size_t)NEXP * HDIM * FDIM];  // w1 fp16
__device__ __align__(128) __half g_w2h[(size_t)NEXP * FDIM * HDIM];  // w2 fp16
__device__ __align__(128) __half g_H[(size_t)NASSIGN * FDIM];        // gelu(x@w1)
__device__ __align__(128) float  g_Y[(size_t)NASSIGN * HDIM];        // h@w2

// ---------------------------------------------------------------------------
// PTX helpers
// ---------------------------------------------------------------------------
__device__ __forceinline__ uint32_t cvta_smem(const void* p) {
    uint32_t a;
    asm("{ .reg .u64 t; cvta.to.shared.u64 t, %1; cvt.u32.u64 %0, t; }"
        : "=r"(a) : "l"(p));
    return a;
}
__device__ __forceinline__ void cp_async16(uint32_t saddr, const void* gaddr) {
    asm volatile("cp.async.cg.shared.global [%0], [%1], 16;"
                 :: "r"(saddr), "l"(gaddr) : "memory");
}
#define CP_COMMIT() asm volatile("cp.async.commit_group;" ::: "memory")
#define CP_WAIT(n)  asm volatile("cp.async.wait_group %0;" :: "n"(n) : "memory")

__device__ __forceinline__ void ldsm_x4(uint32_t addr, uint32_t* r) {
    asm volatile("ldmatrix.sync.aligned.m8n8.x4.shared.b16 {%0,%1,%2,%3}, [%4];"
                 : "=r"(r[0]), "=r"(r[1]), "=r"(r[2]), "=r"(r[3]) : "r"(addr));
}
__device__ __forceinline__ void ldsm_x4_t(uint32_t addr, uint32_t* r) {
    asm volatile("ldmatrix.sync.aligned.m8n8.x4.trans.shared.b16 {%0,%1,%2,%3}, [%4];"
                 : "=r"(r[0]), "=r"(r[1]), "=r"(r[2]), "=r"(r[3]) : "r"(addr));
}
__device__ __forceinline__ void mma_f16(float* d, const uint32_t* a, const uint32_t* b) {
    asm volatile(
        "mma.sync.aligned.m16n8k16.row.col.f32.f16.f16.f32 "
        "{%0,%1,%2,%3}, {%4,%5,%6,%7}, {%8,%9}, {%0,%1,%2,%3};\n"
        : "+f"(d[0]), "+f"(d[1]), "+f"(d[2]), "+f"(d[3])
        : "r"(a[0]), "r"(a[1]), "r"(a[2]), "r"(a[3]), "r"(b[0]), "r"(b[1]));
}

__device__ __forceinline__ uint32_t pack_h2(float x, float y) {
    __half2 h = __floats2half2_rn(x, y);
    return *(uint32_t*)&h;
}
__device__ __forceinline__ float gelu_exact(float v) {
    return 0.5f * v * (1.0f + erff(v * 0.70710678118654752f));
}

// ---------------------------------------------------------------------------
// fp32 -> fp16 convert (grid-stride, 8 elems/thread iteration)
// ---------------------------------------------------------------------------
__global__ void f2h_kernel(const float* __restrict__ src, __half* __restrict__ dst,
                           int n8) {   // n8 = n/8
    for (int i = blockIdx.x * blockDim.x + threadIdx.x; i < n8;
         i += gridDim.x * blockDim.x) {
        const float4* s4 = (const float4*)src + 2 * (size_t)i;
        float4 a = s4[0], b = s4[1];
        uint4 o;
        o.x = pack_h2(a.x, a.y); o.y = pack_h2(a.z, a.w);
        o.z = pack_h2(b.x, b.y); o.w = pack_h2(b.z, b.w);
        ((uint4*)dst)[i] = o;
    }
}

// ---------------------------------------------------------------------------
// Routing with dtype sniffing (int64-declared buffer may actually be int32)
// ---------------------------------------------------------------------------
__global__ void route_kernel(const void* __restrict__ top_experts_raw) {
    const long long* te64 = (const long long*)top_experts_raw;
    const int*       te32 = (const int*)top_experts_raw;
    const int tid = threadIdx.x;

    __shared__ int s_not64;
    if (tid == 0) s_not64 = 0;
    if (tid < NEXP) { g_counts[tid] = 0; g_cursor[tid] = 0; }
    __syncthreads();

    int bad = 0;
    for (int i = tid; i < NASSIGN / 2; i += NTHREADS) {
        long long v = te64[i];
        if (v < 0 || v >= NEXP) bad = 1;
    }
    if (bad) atomicOr(&s_not64, 1);
    __syncthreads();
    const bool is64 = (s_not64 == 0);

    for (int i = tid; i < NASSIGN; i += NTHREADS) {
        int e = is64 ? (int)te64[i] : te32[i];
        atomicAdd(&g_counts[e], 1);
    }
    __syncthreads();
    if (tid == 0) {
        int acc = 0;
        for (int e = 0; e < NEXP; e++) { g_offsets[e] = acc; acc += g_counts[e]; }
        g_offsets[NEXP] = acc;
    }
    __syncthreads();
    for (int i = tid; i < NASSIGN; i += NTHREADS) {
        int e = is64 ? (int)te64[i] : te32[i];
        int pos = g_offsets[e] + atomicAdd(&g_cursor[e], 1);
        g_row_token[pos] = i >> 1;
        g_token_slot[i] = pos;
    }
}

// ---------------------------------------------------------------------------
// Grouped GEMM, fp16 inputs everywhere: cp.async fills, ldmatrix, mma m16n8k16.
// Block 128x128, BK=32, double-buffered, 8 warps (2M x 4N, warp 64x32).
//   GELU=true : A = g_xh rows gathered via g_row_token -> g_H (fp16)
//   GELU=false: A = g_H rows (contiguous slots)        -> g_Y (fp32)
// W fp16 [KDIM, NDIM] row-major per expert.
// ---------------------------------------------------------------------------
template <int KDIM, int NDIM, bool GELU, bool GATHER>
__global__ __launch_bounds__(NTHREADS)
void expert_gemm_h(const __half* __restrict__ A_src, const __half* __restrict__ W) {
    const int e    = blockIdx.z;
    const int base = g_offsets[e];
    const int Me   = g_offsets[e + 1] - base;
    const int m0   = blockIdx.y * BM;
    if (m0 >= Me) return;
    const int n0   = blockIdx.x * BN;

    __shared__ __align__(16) unsigned char sA[2][BM * A_RB];   // 2 x 10240
    __shared__ __align__(16) unsigned char sB[2][BK * B_RB];   // 2 x 8704
    __shared__ int rowSrc[BM];

    const int tid = threadIdx.x;
    const int wid = tid >> 5;
    const int lid = tid & 31;

    for (int r = tid; r < BM; r += NTHREADS) {
        int m = m0 + r;
        int safe_m = (m < Me) ? m : 0;
        rowSrc[r] = GATHER ? g_row_token[base + safe_m] : (base + safe_m);
    }
    __syncthreads();

    const __half* __restrict__ Wt = W + (size_t)e * KDIM * NDIM;

    const uint32_t sbA[2] = { cvta_smem(sA[0]), cvta_smem(sA[1]) };
    const uint32_t sbB[2] = { cvta_smem(sB[0]), cvta_smem(sB[1]) };

    const int NC = KDIM / BK;

    // cp.async coordinates (16B each; 2 A + 2 B per thread per chunk)
    const int a_m0 = (tid + 0 * NTHREADS) >> 2, a_q0 = (tid + 0 * NTHREADS) & 3;
    const int a_m1 = (tid + 1 * NTHREADS) >> 2, a_q1 = (tid + 1 * NTHREADS) & 3;
    const int b_k0 = (tid + 0 * NTHREADS) >> 4, b_c0 = (tid + 0 * NTHREADS) & 15;
    const int b_k1 = (tid + 1 * NTHREADS) >> 4, b_c1 = (tid + 1 * NTHREADS) & 15;

    #define ISSUE(c, buf)                                                           \
        do {                                                                        \
            const int kc0 = (c) * BK;                                               \
            cp_async16(sbA[buf] + a_m0 * A_RB + a_q0 * 16,                          \
                       A_src + (size_t)rowSrc[a_m0] * KDIM + kc0 + a_q0 * 8);       \
            cp_async16(sbA[buf] + a_m1 * A_RB + a_q1 * 16,                          \
                       A_src + (size_t)rowSrc[a_m1] * KDIM + kc0 + a_q1 * 8);       \
            cp_async16(sbB[buf] + b_k0 * B_RB + b_c0 * 16,                          \
                       Wt + (size_t)(kc0 + b_k0) * NDIM + n0 + b_c0 * 8);           \
            cp_async16(sbB[buf] + b_k1 * B_RB + b_c1 * 16,                          \
                       Wt + (size_t)(kc0 + b_k1) * NDIM + n0 + b_c1 * 8);           \
            CP_COMMIT();                                                            \
        } while (0)

    // warp/fragment coordinates
    const int wm  = (wid >> 2) * 64;
    const int wn  = (wid & 3) * 32;
    const int lm8 = lid & 7;
    const int lb1 = (lid >> 3) & 1;
    const int lb2 = lid >> 4;
    const int fr  = lid >> 2;
    const int fc  = lid & 3;

    float acc[4][4][4];
    #pragma unroll
    for (int i = 0; i < 4; i++)
        #pragma unroll
        for (int j = 0; j < 4; j++)
            #pragma unroll
            for (int q = 0; q < 4; q++) acc[i][j][q] = 0.0f;

    ISSUE(0, 0);

    for (int c = 0; c < NC; c++) {
        const int cur = c & 1;
        if (c + 1 < NC) { ISSUE(c + 1, cur ^ 1); CP_WAIT(1); }
        else            { CP_WAIT(0); }
        __syncthreads();

        const uint32_t sa = sbA[cur], sb_ = sbB[cur];
        #pragma unroll
        for (int s = 0; s < 2; s++) {       // two k16 steps per BK=32
            const int k0 = s * 16;
            uint32_t afr[4][4], bfr[4][2];
            #pragma unroll
            for (int i = 0; i < 4; i++) {
                const int row = wm + i * 16 + lm8 + lb1 * 8;
                ldsm_x4(sa + row * A_RB + (k0 + lb2 * 8) * 2, afr[i]);
            }
            #pragma unroll
            for (int j2 = 0; j2 < 2; j2++) {
                const int kk = k0 + lm8 + lb1 * 8;
                const int nn = wn + j2 * 16 + lb2 * 8;
                uint32_t t[4];
                ldsm_x4_t(sb_ + kk * B_RB + nn * 2, t);
                bfr[j2 * 2 + 0][0] = t[0]; bfr[j2 * 2 + 0][1] = t[1];
                bfr[j2 * 2 + 1][0] = t[2]; bfr[j2 * 2 + 1][1] = t[3];
            }
            #pragma unroll
            for (int i = 0; i < 4; i++)
                #pragma unroll
                for (int j = 0; j < 4; j++)
                    mma_f16(acc[i][j], afr[i], bfr[j]);
        }
        __syncthreads();   // protect buffer (c+2 will overwrite cur next iter)
    }

    // Epilogue: acc quad -> rows (fr, fr+8), cols (2fc, 2fc+1)
    #pragma unroll
    for (int i = 0; i < 4; i++) {
        const int mrow0 = m0 + wm + i * 16 + fr;
        #pragma unroll
        for (int j = 0; j < 4; j++) {
            const int col = n0 + wn + j * 8 + fc * 2;
            if (GELU) {
                if (mrow0 < Me) {
                    __half2 h = __floats2half2_rn(gelu_exact(acc[i][j][0]),
                                                  gelu_exact(acc[i][j][1]));
                    *(__half2*)(g_H + (size_t)(base + mrow0) * NDIM + col) = h;
                }
                if (mrow0 + 8 < Me) {
                    __half2 h = __floats2half2_rn(gelu_exact(acc[i][j][2]),
                                                  gelu_exact(acc[i][j][3]));
                    *(__half2*)(g_H + (size_t)(base + mrow0 + 8) * NDIM + col) = h;
                }
            } else {
                if (mrow0 < Me) {
                    *(float2*)(g_Y + (size_t)(base + mrow0) * NDIM + col) =
                        make_float2(acc[i][j][0], acc[i][j][1]);
                }
                if (mrow0 + 8 < Me) {
                    *(float2*)(g_Y + (size_t)(base + mrow0 + 8) * NDIM + col) =
                        make_float2(acc[i][j][2], acc[i][j][3]);
                }
            }
        }
    }
    #undef ISSUE
}

// ---------------------------------------------------------------------------
// Combine: out[t] = ew[t,0]*Y[slot(t,0)] + ew[t,1]*Y[slot(t,1)]
// ---------------------------------------------------------------------------
__global__ void combine_kernel(const float* __restrict__ ew, float* __restrict__ out) {
    int idx = blockIdx.x * blockDim.x + threadIdx.x;
    if (idx >= T_TOK * (HDIM / 4)) return;
    int t  = idx / (HDIM / 4);
    int c4 = (idx % (HDIM / 4)) * 4;
    float w0 = ew[t * 2 + 0];
    float w1 = ew[t * 2 + 1];
    int   s0 = g_token_slot[t * 2 + 0];
    int   s1 = g_token_slot[t * 2 + 1];
    float4 y0 = *(const float4*)(g_Y + (size_t)s0 * HDIM + c4);
    float4 y1 = *(const float4*)(g_Y + (size_t)s1 * HDIM + c4);
    float4 o;
    o.x = w0 * y0.x + w1 * y1.x;
    o.y = w0 * y0.y + w1 * y1.y;
    o.z = w0 * y0.z + w1 * y1.z;
    o.w = w0 * y0.w + w1 * y1.w;
    *(float4*)(out + (size_t)t * HDIM + c4) = o;
}

// ---------------------------------------------------------------------------
// kernel_launch: route + converts -> GEMM1 -> GEMM2 -> combine
// ---------------------------------------------------------------------------
extern "C" void kernel_launch(void* const* d_in, const int* in_sizes, int n_in,
                              void* d_out, int out_size) {
    const float* x   = (const float*)d_in[0];
    const float* ew  = (const float*)d_in[2];
    const void*  te  = d_in[3];
    const float* w1  = (const float*)d_in[4];
    const float* w2  = (const float*)d_in[5];
    float*       out = (float*)d_out;

    route_kernel<<<1, NTHREADS>>>(te);

    // fp32 -> fp16 converts (grid-stride)
    __half* xh; cudaGetSymbolAddress((void**)&xh, g_xh);
    __half* w1h; cudaGetSymbolAddress((void**)&w1h, g_w1h);
    __half* w2h; cudaGetSymbolAddress((void**)&w2h, g_w2h);
    __half* Hh; cudaGetSymbolAddress((void**)&Hh, g_H);

    f2h_kernel<<<1024, NTHREADS>>>(x, xh, (T_TOK * HDIM) / 8);
    f2h_kernel<<<8192, NTHREADS>>>(w1, w1h, (NEXP * HDIM * FDIM) / 8);
    f2h_kernel<<<8192, NTHREADS>>>(w2, w2h, (NEXP * FDIM * HDIM) / 8);

    // GEMM1: gathered xh [Me,H] x w1h[e] [H,F] -> gelu -> g_H (fp16)
    dim3 g1(FDIM / BN, NASSIGN / BM, NEXP);   // 32 x 32 x 8
    expert_gemm_h<HDIM, FDIM, true, true><<<g1, NTHREADS>>>(xh, w1h);

    // GEMM2: g_H [Me,F] x w2h[e] [F,H] -> g_Y (fp32)
    dim3 g2(HDIM / BN, NASSIGN / BM, NEXP);   // 8 x 32 x 8
    expert_gemm_h<FDIM, HDIM, false, false><<<g2, NTHREADS>>>(Hh, w2h);

    // Combine into output
    int total = T_TOK * (HDIM / 4);
    combine_kernel<<<(total + NTHREADS - 1) / NTHREADS, NTHREADS>>>(ew, out);
}